// round 14
// baseline (speedup 1.0000x reference)
#include <cuda_runtime.h>

// NeRF volume rendering compositing — round 14: L1 prefetch of rgb.
// Base = round-13 best (12.58us): two rays/warp (16-lane segments),
// 64-sample rounds, 4 samples/lane, float4 default-cached loads, scan-
// predicated rgb, tau=1e-4, 128-thread blocks. Single change: each lane
// issues prefetch.global.L1 on its rgb base address BEFORE the exp/scan
// phase (addresses are scan-independent; lane stride 48B < 128B line, so
// one prefetch/lane covers the segment's whole 768B rgb span). The
// predicated rgb LDGs after the scan then hit L1 (~39cyc) instead of a
// second serialized L2 exposure (~234cyc). Zero extra registers — this is
// the R11 speculation win without its occupancy cost.
// Inputs (metadata order):
//   d_in[0]: sigma  [B, S]    float32   (B=65536, S=512)
//   d_in[1]: dists  [B, S]    float32
//   d_in[2]: rgb    [B, S, 3] float32
//   d_in[3]: bg_col [3]       float32
// Output: rgb_map [B, 3] float32
//
//   x = sigma*dists*25; alpha = 1-exp(-x); T = excl cumprod(exp(-x)+1e-10)
//   w = alpha*T; out_c = sum w*clip(rgb,0,1) + (1-sum w)*bg_c
// Early termination at T < 1e-4: skipped mass telescopes to < 1e-4 abs;
// measured rel_err 6.38e-5 vs the 1e-3 gate.

#define DIST_SCALE 25.0f
#define T_THRESH   1e-4f
#define FULLMASK   0xffffffffu
#define SEGW       16

__device__ __forceinline__ float clip01(float v) {
    return fminf(fmaxf(v, 0.0f), 1.0f);
}

__global__ __launch_bounds__(128, 16)
void nerf_composite_kernel(const float4* __restrict__ sigma4,
                           const float4* __restrict__ dists4,
                           const float4* __restrict__ rgb4,
                           const float*  __restrict__ bg,
                           float*        __restrict__ out,
                           int B)
{
    const int warp  = (int)((blockIdx.x * (unsigned)blockDim.x + threadIdx.x) >> 5);
    const int lane  = threadIdx.x & 31;
    const int slane = lane & (SEGW - 1);        // lane within 16-lane segment
    const int ray   = warp * 2 + (lane >> 4);   // one ray per half-warp
    if (ray >= B) return;

    float T_run = 1.0f;          // uniform within the segment
    float accW = 0.0f, accR = 0.0f, accG = 0.0f, accB = 0.0f;

    // S = 512 samples = 8 rounds of 64 (4 samples/lane, float4 loads).
    #pragma unroll 1
    for (int k = 0; k < 8; ++k) {
        const int idx  = ray * 128 + k * 16 + slane;     // float4 idx: sigma/dists
        const int ridx = ray * 384 + k * 48 + slane * 3; // float4 idx: rgb

        const float4 sg = sigma4[idx];
        const float4 dt = dists4[idx];

        // Prefetch this lane's rgb line into L1 NOW (scan-independent
        // address). One prefetch/lane covers all lines of the segment's
        // rgb span (48B lane stride < 128B line).
        asm volatile("prefetch.global.L1 [%0];" :: "l"(rgb4 + ridx));

        // Transmittance factors f = exp(-sigma*dist*25)
        const float f0 = __expf(-DIST_SCALE * sg.x * dt.x);
        const float f1 = __expf(-DIST_SCALE * sg.y * dt.y);
        const float f2 = __expf(-DIST_SCALE * sg.z * dt.z);
        const float f3 = __expf(-DIST_SCALE * sg.w * dt.w);

        const float g0 = f0 + 1e-10f;
        const float g1 = f1 + 1e-10f;
        const float g2 = f2 + 1e-10f;
        const float g3 = f3 + 1e-10f;

        float w0 = (1.0f - f0);
        float t  = g0;
        float w1 = (1.0f - f1) * t;  t *= g1;
        float w2 = (1.0f - f2) * t;  t *= g2;
        float w3 = (1.0f - f3) * t;
        const float p = t * g3;      // product of this lane's 4 factors

        // Segment (width-16) inclusive prefix product of p
        float incl = p;
        #pragma unroll
        for (int off = 1; off < SEGW; off <<= 1) {
            const float v = __shfl_up_sync(FULLMASK, incl, off, SEGW);
            if (slane >= off) incl *= v;
        }
        float excl = __shfl_up_sync(FULLMASK, incl, 1, SEGW);
        if (slane == 0) excl = 1.0f;
        const float total = __shfl_sync(FULLMASK, incl, SEGW - 1, SEGW);

        const float Tl = T_run * excl;   // transmittance at this lane's first sample

        // Lanes with negligible remaining transmittance skip rgb traffic.
        if (Tl >= T_THRESH) {
            const float4 q0 = rgb4[ridx + 0];
            const float4 q1 = rgb4[ridx + 1];
            const float4 q2 = rgb4[ridx + 2];

            w0 *= Tl; w1 *= Tl; w2 *= Tl; w3 *= Tl;

            accR += w0 * clip01(q0.x) + w1 * clip01(q0.w)
                  + w2 * clip01(q1.z) + w3 * clip01(q2.y);
            accG += w0 * clip01(q0.y) + w1 * clip01(q1.x)
                  + w2 * clip01(q1.w) + w3 * clip01(q2.z);
            accB += w0 * clip01(q0.z) + w1 * clip01(q1.y)
                  + w2 * clip01(q2.x) + w3 * clip01(q2.w);
            accW += w0 + w1 + w2 + w3;
        }

        T_run *= total;                          // stays segment-uniform
        const bool done = (T_run < T_THRESH);
        if (__all_sync(FULLMASK, done)) break;   // warp-uniform early exit
    }

    // Segment (width-16) reduction
    #pragma unroll
    for (int off = SEGW / 2; off >= 1; off >>= 1) {
        accW += __shfl_down_sync(FULLMASK, accW, off, SEGW);
        accR += __shfl_down_sync(FULLMASK, accR, off, SEGW);
        accG += __shfl_down_sync(FULLMASK, accG, off, SEGW);
        accB += __shfl_down_sync(FULLMASK, accB, off, SEGW);
    }

    if (slane == 0) {
        const float rem = 1.0f - accW;
        out[ray * 3 + 0] = accR + rem * __ldg(&bg[0]);
        out[ray * 3 + 1] = accG + rem * __ldg(&bg[1]);
        out[ray * 3 + 2] = accB + rem * __ldg(&bg[2]);
    }
}

extern "C" void kernel_launch(void* const* d_in, const int* in_sizes, int n_in,
                              void* d_out, int out_size)
{
    const float4* sigma4 = (const float4*)d_in[0];
    const float4* dists4 = (const float4*)d_in[1];
    const float4* rgb4   = (const float4*)d_in[2];
    const float*  bg     = (const float*) d_in[3];
    float*        out    = (float*)d_out;

    const int B = in_sizes[0] / 512;           // 65536 rays
    const int threads = 128;                    // 4 warps/block -> 8 rays/block
    const int blocks  = (B + 7) / 8;            // 8192 blocks

    nerf_composite_kernel<<<blocks, threads>>>(sigma4, dists4, rgb4, bg, out, B);
}